// round 5
// baseline (speedup 1.0000x reference)
#include <cuda_runtime.h>
#include <cstdint>

// Problem constants
#define BSZ   2048
#define DIM   1024
#define DWM   512
#define WIN   256
#define NH    8
#define HD    64
#define QKV_LD 1536
#define ATT_SCALE 0.125f
#define NCH   4
#define CB    (BSZ / NCH)   // 512 rows per chunk

// Scratch (device globals: allocation-free rule)
__device__ float g_qkv[(size_t)BSZ * QKV_LD];   // 12 MB
__device__ float g_att[(size_t)BSZ * DWM];      // 4 MB
__device__ int   g_bool_mode;                   // 0=uint8, 1=int32, 2=float32

// ---------------- bool dtype detection ---------------------------------------
__global__ void detect_bool_kernel(const unsigned char* __restrict__ valid)
{
    unsigned char b0 = valid[0], b1 = valid[1];
    g_bool_mode = (b0 == 0) ? 2 : (b1 != 0 ? 0 : 1);
}
__device__ __forceinline__ bool read_bool(const void* p, long idx, int mode)
{
    if (mode == 1) return ((const int*)p)[idx] != 0;
    if (mode == 2) return ((const float*)p)[idx] != 0.0f;
    return ((const unsigned char*)p)[idx] != 0;
}

// ---------------- tf32 helpers ------------------------------------------------
__device__ __forceinline__ uint32_t f2tf32(float f) {
    uint32_t u;
    asm("cvt.rna.tf32.f32 %0, %1;" : "=r"(u) : "f"(f));
    return u;
}
__device__ __forceinline__ void mma_tf32(float* d, const uint32_t* a, const uint32_t* b) {
    asm volatile(
        "mma.sync.aligned.m16n8k8.row.col.f32.tf32.tf32.f32 "
        "{%0,%1,%2,%3},{%4,%5,%6,%7},{%8,%9},{%0,%1,%2,%3};\n"
        : "+f"(d[0]), "+f"(d[1]), "+f"(d[2]), "+f"(d[3])
        : "r"(a[0]), "r"(a[1]), "r"(a[2]), "r"(a[3]), "r"(b[0]), "r"(b[1]));
}

// ===================== tf32 mma.sync GEMM (NT + bias) =========================
#define BM 128
#define BN 64
#define BK 32
#define A_FLOATS (BM * BK)
#define B_FLOATS (BN * BK)
#define BUF_FLOATS (A_FLOATS + B_FLOATS)
#define TCSM_BYTES (2 * BUF_FLOATS * 4)

__device__ __forceinline__ void tc_gemm_body(
    const float* __restrict__ A, const float* __restrict__ Bw,
    const float* __restrict__ bias, float* __restrict__ C,
    int K, int ldc, int rowBase, int colB, int colC, int niter)
{
    extern __shared__ float smem[];
    const int tid  = threadIdx.x;
    const int lane = tid & 31;
    const int warp = tid >> 5;
    const int g    = lane >> 2;
    const int tg   = lane & 3;
    const int wm   = (warp >> 1) * 32;
    const int wn   = (warp & 1) * 32;

    const float* Abase = A  + (size_t)rowBase * K;
    const float* Bbase = Bw + (size_t)colB  * K;

    float acc[2][4][4];
    #pragma unroll
    for (int mt = 0; mt < 2; ++mt)
        #pragma unroll
        for (int nt = 0; nt < 4; ++nt)
            #pragma unroll
            for (int r = 0; r < 4; ++r) acc[mt][nt][r] = 0.f;

    float4 pa[4], pb[2];

    #pragma unroll
    for (int i = 0; i < 4; ++i) {
        int idx = tid + (i << 8), row = idx >> 3, q = idx & 7;
        pa[i] = *(const float4*)(Abase + (size_t)row * K + (q << 2));
    }
    #pragma unroll
    for (int i = 0; i < 2; ++i) {
        int idx = tid + (i << 8), row = idx >> 3, q = idx & 7;
        pb[i] = *(const float4*)(Bbase + (size_t)row * K + (q << 2));
    }
    {
        float* Abuf = smem;
        float* Bbuf = smem + A_FLOATS;
        #pragma unroll
        for (int i = 0; i < 4; ++i) {
            int idx = tid + (i << 8), row = idx >> 3, q = idx & 7;
            uint4 t;
            t.x = f2tf32(pa[i].x); t.y = f2tf32(pa[i].y);
            t.z = f2tf32(pa[i].z); t.w = f2tf32(pa[i].w);
            *(uint4*)(Abuf + row * BK + ((q ^ (row & 7)) << 2)) = t;
        }
        #pragma unroll
        for (int i = 0; i < 2; ++i) {
            int idx = tid + (i << 8), row = idx >> 3, q = idx & 7;
            uint4 t;
            t.x = f2tf32(pb[i].x); t.y = f2tf32(pb[i].y);
            t.z = f2tf32(pb[i].z); t.w = f2tf32(pb[i].w);
            *(uint4*)(Bbuf + row * BK + ((q ^ (row & 7)) << 2)) = t;
        }
    }
    __syncthreads();

    for (int it = 0; it < niter; ++it) {
        const int buf = it & 1;
        if (it + 1 < niter) {
            const float* An = Abase + (it + 1) * BK;
            const float* Bn = Bbase + (it + 1) * BK;
            #pragma unroll
            for (int i = 0; i < 4; ++i) {
                int idx = tid + (i << 8), row = idx >> 3, q = idx & 7;
                pa[i] = *(const float4*)(An + (size_t)row * K + (q << 2));
            }
            #pragma unroll
            for (int i = 0; i < 2; ++i) {
                int idx = tid + (i << 8), row = idx >> 3, q = idx & 7;
                pb[i] = *(const float4*)(Bn + (size_t)row * K + (q << 2));
            }
        }
        {
            const uint32_t* Abuf = (const uint32_t*)(smem + buf * BUF_FLOATS);
            const uint32_t* Bbuf = Abuf + A_FLOATS;
            #pragma unroll
            for (int ks = 0; ks < 4; ++ks) {
                uint32_t af[2][4], bf[4][2];
                const int g0 = ((2 * ks) ^ g) << 2;
                const int g1 = ((2 * ks + 1) ^ g) << 2;
                #pragma unroll
                for (int mt = 0; mt < 2; ++mt) {
                    int r0 = wm + mt * 16 + g;
                    int r1 = r0 + 8;
                    af[mt][0] = Abuf[r0 * BK + g0 + tg];
                    af[mt][1] = Abuf[r1 * BK + g0 + tg];
                    af[mt][2] = Abuf[r0 * BK + g1 + tg];
                    af[mt][3] = Abuf[r1 * BK + g1 + tg];
                }
                #pragma unroll
                for (int nt = 0; nt < 4; ++nt) {
                    int n = wn + nt * 8 + g;
                    bf[nt][0] = Bbuf[n * BK + g0 + tg];
                    bf[nt][1] = Bbuf[n * BK + g1 + tg];
                }
                #pragma unroll
                for (int mt = 0; mt < 2; ++mt)
                    #pragma unroll
                    for (int nt = 0; nt < 4; ++nt)
                        mma_tf32(acc[mt][nt], af[mt], bf[nt]);
            }
        }
        if (it + 1 < niter) {
            float* Abuf = smem + (buf ^ 1) * BUF_FLOATS;
            float* Bbuf = Abuf + A_FLOATS;
            #pragma unroll
            for (int i = 0; i < 4; ++i) {
                int idx = tid + (i << 8), row = idx >> 3, q = idx & 7;
                uint4 t;
                t.x = f2tf32(pa[i].x); t.y = f2tf32(pa[i].y);
                t.z = f2tf32(pa[i].z); t.w = f2tf32(pa[i].w);
                *(uint4*)(Abuf + row * BK + ((q ^ (row & 7)) << 2)) = t;
            }
            #pragma unroll
            for (int i = 0; i < 2; ++i) {
                int idx = tid + (i << 8), row = idx >> 3, q = idx & 7;
                uint4 t;
                t.x = f2tf32(pb[i].x); t.y = f2tf32(pb[i].y);
                t.z = f2tf32(pb[i].z); t.w = f2tf32(pb[i].w);
                *(uint4*)(Bbuf + row * BK + ((q ^ (row & 7)) << 2)) = t;
            }
            __syncthreads();
        }
    }

    #pragma unroll
    for (int mt = 0; mt < 2; ++mt) {
        #pragma unroll
        for (int nt = 0; nt < 4; ++nt) {
            int r0  = rowBase + wm + mt * 16 + g;
            int col = wn + nt * 8 + tg * 2;
            float b0 = bias[colB + col], b1 = bias[colB + col + 1];
            float2 v0 = make_float2(acc[mt][nt][0] + b0, acc[mt][nt][1] + b1);
            float2 v1 = make_float2(acc[mt][nt][2] + b0, acc[mt][nt][3] + b1);
            *(float2*)(C + (size_t)r0 * ldc + colC + col) = v0;
            *(float2*)(C + (size_t)(r0 + 8) * ldc + colC + col) = v1;
        }
    }
}

__global__ __launch_bounds__(256) void qkv_gemm_tc(
    const float* __restrict__ x,
    const float* __restrict__ Wq, const float* __restrict__ bq,
    const float* __restrict__ Wk, const float* __restrict__ bk,
    const float* __restrict__ Wv, const float* __restrict__ bv,
    int rowOff)
{
    const int y  = blockIdx.y;
    const int z  = y >> 3;
    const int nc = (y & 7) * BN;
    const float* Bw = (z == 0) ? Wq : (z == 1) ? Wk : Wv;
    const float* bi = (z == 0) ? bq : (z == 1) ? bk : bv;
    tc_gemm_body(x, Bw, bi, g_qkv, DIM, QKV_LD,
                 rowOff + blockIdx.x * BM, nc, z * DWM + nc, DIM / BK);
}

__global__ __launch_bounds__(256) void out_gemm_tc(
    const float* __restrict__ Wo, const float* __restrict__ bo,
    float* __restrict__ y, int rowOff)
{
    tc_gemm_body(g_att, Wo, bo, y, DWM, DIM,
                 rowOff + blockIdx.x * BM, blockIdx.y * BN, blockIdx.y * BN, DWM / BK);
}

// ---------------- Attention kernel: one CTA per batch row --------------------
__global__ __launch_bounds__(256) void attn_kernel(
    const float* __restrict__ wmK, const float* __restrict__ wmV,
    const void* __restrict__ validIn,
    const void* __restrict__ resetIn,
    const int* __restrict__ ptrIn,
    int bOff)
{
    __shared__ float q_s[DWM];
    __shared__ float att_s[NH][WIN];
    __shared__ unsigned char valid_s[WIN];

    const int b    = bOff + blockIdx.x;
    const int tid  = threadIdx.x;
    const int lane = tid & 31;
    const int warp = tid >> 5;

    const int mode = g_bool_mode;
    const bool rs = read_bool(resetIn, b, mode);
    const int  p  = rs ? 0 : ptrIn[b];

    const float* qrow  = g_qkv + (size_t)b * QKV_LD;
    const float* knew  = qrow + DWM;
    const float* vnew  = qrow + 2 * DWM;
    const float* Kbase = wmK + (size_t)b * WIN * DWM;
    const float* Vbase = wmV + (size_t)b * WIN * DWM;

    for (int i = tid; i < DWM; i += 256) q_s[i] = qrow[i];
    if (tid < WIN)
        valid_s[tid] = read_bool(validIn, (size_t)b * WIN + tid, mode) ? 1 : 0;
    __syncthreads();

    const float NEG_INF = __int_as_float(0xff800000);

    // ---- phase 1: logits (uniform over stored K; slot p patched after) ----
    {
        const int h = warp;
        float2 qv = *(const float2*)(q_s + h * HD + lane * 2);
        const float2* kp = (const float2*)(Kbase + h * HD + lane * 2);
        for (int w0 = 0; w0 < WIN; w0 += 8) {
            float s[8];
            #pragma unroll
            for (int u = 0; u < 8; ++u) {
                float2 kv = __ldcs(kp + (size_t)(w0 + u) * (DWM / 2));
                s[u] = kv.x * qv.x + kv.y * qv.y;
            }
            #pragma unroll
            for (int u = 0; u < 8; ++u) {
                #pragma unroll
                for (int o = 16; o > 0; o >>= 1)
                    s[u] += __shfl_xor_sync(0xffffffffu, s[u], o);
            }
            if (lane == 0) {
                #pragma unroll
                for (int u = 0; u < 8; ++u) {
                    int w = w0 + u;
                    bool val = !rs && (valid_s[w] != 0);
                    att_s[h][w] = val ? s[u] * ATT_SCALE : NEG_INF;
                }
            }
        }
        {
            float2 kv = *(const float2*)(knew + h * HD + lane * 2);
            float s = kv.x * qv.x + kv.y * qv.y;
            #pragma unroll
            for (int o = 16; o > 0; o >>= 1)
                s += __shfl_xor_sync(0xffffffffu, s, o);
            if (lane == 0) att_s[h][p] = s * ATT_SCALE;
        }
    }
    __syncthreads();

    // ---- phase 2: per-head softmax (warp h) ----
    {
        const int h = warp;
        float e[8];
        float m = NEG_INF;
        #pragma unroll
        for (int j = 0; j < 8; ++j) {
            e[j] = att_s[h][lane + 32 * j];
            m = fmaxf(m, e[j]);
        }
        #pragma unroll
        for (int o = 16; o > 0; o >>= 1)
            m = fmaxf(m, __shfl_xor_sync(0xffffffffu, m, o));
        float sum = 0.f;
        #pragma unroll
        for (int j = 0; j < 8; ++j) {
            e[j] = __expf(e[j] - m);
            sum += e[j];
        }
        #pragma unroll
        for (int o = 16; o > 0; o >>= 1)
            sum += __shfl_xor_sync(0xffffffffu, sum, o);
        float inv = (sum > 0.f) ? (1.0f / sum) : 0.f;
        #pragma unroll
        for (int j = 0; j < 8; ++j)
            att_s[h][lane + 32 * j] = e[j] * inv;
    }
    __syncthreads();

    // ---- phase 3: AV, uniform over stored V; correction for slot p ----
    {
        const int d = tid * 2;
        const int h = tid >> 5;
        float ax = 0.f, ay = 0.f;
        const float2* vp = (const float2*)(Vbase + d);
        for (int w0 = 0; w0 < WIN; w0 += 8) {
            float2 vv[8];
            #pragma unroll
            for (int u = 0; u < 8; ++u)
                vv[u] = __ldcs(vp + (size_t)(w0 + u) * (DWM / 2));
            #pragma unroll
            for (int u = 0; u < 8; ++u) {
                float pw = att_s[h][w0 + u];
                ax = fmaf(pw, vv[u].x, ax);
                ay = fmaf(pw, vv[u].y, ay);
            }
        }
        {
            float2 vold = *(const float2*)(Vbase + (size_t)p * DWM + d);
            float2 vn   = *(const float2*)(vnew + d);
            float pw = att_s[h][p];
            ax = fmaf(pw, vn.x - vold.x, ax);
            ay = fmaf(pw, vn.y - vold.y, ay);
        }
        *(float2*)(g_att + (size_t)b * DWM + d) = make_float2(ax, ay);
    }
}

// ---------------- launcher: chunked pipeline across 3 streams ----------------
extern "C" void kernel_launch(void* const* d_in, const int* in_sizes, int n_in,
                              void* d_out, int out_size)
{
    const float* x     = (const float*)d_in[0];
    const void*  reset = d_in[1];
    const float* wmK   = (const float*)d_in[2];
    const float* wmV   = (const float*)d_in[3];
    const void*  valid = d_in[4];
    const int*   ptr   = (const int*)d_in[5];
    const float* Wq    = (const float*)d_in[6];
    const float* bq    = (const float*)d_in[7];
    const float* Wk    = (const float*)d_in[8];
    const float* bk    = (const float*)d_in[9];
    const float* Wv    = (const float*)d_in[10];
    const float* bv    = (const float*)d_in[11];
    const float* Wo    = (const float*)d_in[12];
    const float* bo    = (const float*)d_in[13];
    float*       y     = (float*)d_out;

    // Persistent side streams + events (created once, outside capture;
    // handles are resources, not work — kernel work stays deterministic).
    static cudaStream_t s1 = nullptr, s2 = nullptr;
    static cudaEvent_t evRoot, evQ[NCH], evA[NCH], evJ1, evJ2;
    if (s1 == nullptr) {
        cudaStreamCreateWithFlags(&s1, cudaStreamNonBlocking);
        cudaStreamCreateWithFlags(&s2, cudaStreamNonBlocking);
        cudaEventCreateWithFlags(&evRoot, cudaEventDisableTiming);
        cudaEventCreateWithFlags(&evJ1, cudaEventDisableTiming);
        cudaEventCreateWithFlags(&evJ2, cudaEventDisableTiming);
        for (int i = 0; i < NCH; ++i) {
            cudaEventCreateWithFlags(&evQ[i], cudaEventDisableTiming);
            cudaEventCreateWithFlags(&evA[i], cudaEventDisableTiming);
        }
    }

    cudaStream_t s0 = 0;  // capture-origin (legacy default) stream

    detect_bool_kernel<<<1, 1, 0, s0>>>((const unsigned char*)valid);
    cudaEventRecord(evRoot, s0);
    cudaStreamWaitEvent(s1, evRoot, 0);
    cudaStreamWaitEvent(s2, evRoot, 0);

    for (int c = 0; c < NCH; ++c) {
        dim3 gQKV(CB / BM, 24);
        qkv_gemm_tc<<<gQKV, 256, TCSM_BYTES, s0>>>(x, Wq, bq, Wk, bk, Wv, bv, c * CB);
        cudaEventRecord(evQ[c], s0);

        cudaStreamWaitEvent(s1, evQ[c], 0);
        attn_kernel<<<CB, 256, 0, s1>>>(wmK, wmV, valid, reset, ptr, c * CB);
        cudaEventRecord(evA[c], s1);

        cudaStreamWaitEvent(s2, evA[c], 0);
        dim3 gOut(CB / BM, DIM / BN);
        out_gemm_tc<<<gOut, 256, TCSM_BYTES, s2>>>(Wo, bo, y, c * CB);
    }

    // join side streams back into the origin stream
    cudaEventRecord(evJ1, s1);
    cudaEventRecord(evJ2, s2);
    cudaStreamWaitEvent(s0, evJ1, 0);
    cudaStreamWaitEvent(s0, evJ2, 0);
}

// round 6
// speedup vs baseline: 1.4310x; 1.4310x over previous
#include <cuda_runtime.h>
#include <cstdint>

// Problem constants
#define BSZ   2048
#define DIM   1024
#define DWM   512
#define WIN   256
#define NH    8
#define HD    64
#define QKV_LD 1536
#define ATT_SCALE 0.125f

// Scratch (device globals: allocation-free rule)
__device__ float g_qkv[(size_t)BSZ * QKV_LD];   // 12 MB
__device__ float g_att[(size_t)BSZ * DWM];      // 4 MB

// ---------------- bool dtype helpers ------------------------------------------
// bool arrays may be stored as uint8 / int32 / float32; wm_valid is all-True so
// its first bytes identify the dtype. Computed per-CTA (cheap, deterministic).
__device__ __forceinline__ int bool_mode(const unsigned char* valid)
{
    unsigned char b0 = valid[0], b1 = valid[1];
    return (b0 == 0) ? 2 : (b1 != 0 ? 0 : 1);   // 0=u8, 1=i32, 2=f32
}
__device__ __forceinline__ bool read_bool(const void* p, long idx, int mode)
{
    if (mode == 1) return ((const int*)p)[idx] != 0;
    if (mode == 2) return ((const float*)p)[idx] != 0.0f;
    return ((const unsigned char*)p)[idx] != 0;
}

// ---------------- tf32 helpers ------------------------------------------------
__device__ __forceinline__ uint32_t f2tf32(float f) {
    uint32_t u;
    asm("cvt.rna.tf32.f32 %0, %1;" : "=r"(u) : "f"(f));
    return u;
}
__device__ __forceinline__ void mma_tf32(float* d, const uint32_t* a, const uint32_t* b) {
    asm volatile(
        "mma.sync.aligned.m16n8k8.row.col.f32.tf32.tf32.f32 "
        "{%0,%1,%2,%3},{%4,%5,%6,%7},{%8,%9},{%0,%1,%2,%3};\n"
        : "+f"(d[0]), "+f"(d[1]), "+f"(d[2]), "+f"(d[3])
        : "r"(a[0]), "r"(a[1]), "r"(a[2]), "r"(a[3]), "r"(b[0]), "r"(b[1]));
}

// ===================== tf32 mma.sync GEMM (NT + bias) =========================
// C[m,n] = sum_k A[m,k]*B[n,k] + bias[n]
// CTA tile 128x128, K-tile 32, 256 threads = 8 warps (2m x 4n), warp tile 64x32.
#define BM 128
#define BN 128
#define BK 32
#define A_FLOATS (BM * BK)               // 4096
#define B_FLOATS (BN * BK)               // 4096
#define BUF_FLOATS (A_FLOATS + B_FLOATS) // 8192
#define TCSM_BYTES (2 * BUF_FLOATS * 4)  // 65536 (opt-in)

__device__ __forceinline__ void tc_gemm_body(
    const float* __restrict__ A, const float* __restrict__ Bw,
    const float* __restrict__ bias, float* __restrict__ C,
    int K, int ldc, int rowBase, int colB, int colC, int niter)
{
    extern __shared__ float smem[];
    const int tid  = threadIdx.x;
    const int lane = tid & 31;
    const int warp = tid >> 5;
    const int g    = lane >> 2;          // 0..7
    const int tg   = lane & 3;           // 0..3
    const int wm   = (warp >> 2) * 64;   // 0,64
    const int wn   = (warp & 3) * 32;    // 0,32,64,96

    const float* Abase = A  + (size_t)rowBase * K;
    const float* Bbase = Bw + (size_t)colB  * K;

    float acc[4][4][4];
    #pragma unroll
    for (int mt = 0; mt < 4; ++mt)
        #pragma unroll
        for (int nt = 0; nt < 4; ++nt)
            #pragma unroll
            for (int r = 0; r < 4; ++r) acc[mt][nt][r] = 0.f;

    float4 pa[4], pb[4];

    // ---- prefetch + store tile 0 ----
    #pragma unroll
    for (int i = 0; i < 4; ++i) {
        int idx = tid + (i << 8), row = idx >> 3, q = idx & 7;
        pa[i] = *(const float4*)(Abase + (size_t)row * K + (q << 2));
        pb[i] = *(const float4*)(Bbase + (size_t)row * K + (q << 2));
    }
    {
        float* Abuf = smem;
        float* Bbuf = smem + A_FLOATS;
        #pragma unroll
        for (int i = 0; i < 4; ++i) {
            int idx = tid + (i << 8), row = idx >> 3, q = idx & 7;
            uint4 ta, tb;
            ta.x = f2tf32(pa[i].x); ta.y = f2tf32(pa[i].y);
            ta.z = f2tf32(pa[i].z); ta.w = f2tf32(pa[i].w);
            tb.x = f2tf32(pb[i].x); tb.y = f2tf32(pb[i].y);
            tb.z = f2tf32(pb[i].z); tb.w = f2tf32(pb[i].w);
            int soff = row * BK + ((q ^ (row & 7)) << 2);
            *(uint4*)(Abuf + soff) = ta;
            *(uint4*)(Bbuf + soff) = tb;
        }
    }
    __syncthreads();

    for (int it = 0; it < niter; ++it) {
        const int buf = it & 1;
        if (it + 1 < niter) {
            const float* An = Abase + (it + 1) * BK;
            const float* Bn = Bbase + (it + 1) * BK;
            #pragma unroll
            for (int i = 0; i < 4; ++i) {
                int idx = tid + (i << 8), row = idx >> 3, q = idx & 7;
                pa[i] = *(const float4*)(An + (size_t)row * K + (q << 2));
                pb[i] = *(const float4*)(Bn + (size_t)row * K + (q << 2));
            }
        }
        {
            const uint32_t* Abuf = (const uint32_t*)(smem + buf * BUF_FLOATS);
            const uint32_t* Bbuf = Abuf + A_FLOATS;
            #pragma unroll
            for (int ks = 0; ks < 4; ++ks) {
                uint32_t af[4][4], bf[4][2];
                const int g0 = ((2 * ks) ^ g) << 2;
                const int g1 = ((2 * ks + 1) ^ g) << 2;
                #pragma unroll
                for (int mt = 0; mt < 4; ++mt) {
                    int r0 = wm + mt * 16 + g;
                    int r1 = r0 + 8;
                    af[mt][0] = Abuf[r0 * BK + g0 + tg];
                    af[mt][1] = Abuf[r1 * BK + g0 + tg];
                    af[mt][2] = Abuf[r0 * BK + g1 + tg];
                    af[mt][3] = Abuf[r1 * BK + g1 + tg];
                }
                #pragma unroll
                for (int nt = 0; nt < 4; ++nt) {
                    int n = wn + nt * 8 + g;
                    bf[nt][0] = Bbuf[n * BK + g0 + tg];
                    bf[nt][1] = Bbuf[n * BK + g1 + tg];
                }
                #pragma unroll
                for (int mt = 0; mt < 4; ++mt)
                    #pragma unroll
                    for (int nt = 0; nt < 4; ++nt)
                        mma_tf32(acc[mt][nt], af[mt], bf[nt]);
            }
        }
        if (it + 1 < niter) {
            float* Abuf = smem + (buf ^ 1) * BUF_FLOATS;
            float* Bbuf = Abuf + A_FLOATS;
            #pragma unroll
            for (int i = 0; i < 4; ++i) {
                int idx = tid + (i << 8), row = idx >> 3, q = idx & 7;
                uint4 ta, tb;
                ta.x = f2tf32(pa[i].x); ta.y = f2tf32(pa[i].y);
                ta.z = f2tf32(pa[i].z); ta.w = f2tf32(pa[i].w);
                tb.x = f2tf32(pb[i].x); tb.y = f2tf32(pb[i].y);
                tb.z = f2tf32(pb[i].z); tb.w = f2tf32(pb[i].w);
                int soff = row * BK + ((q ^ (row & 7)) << 2);
                *(uint4*)(Abuf + soff) = ta;
                *(uint4*)(Bbuf + soff) = tb;
            }
            __syncthreads();
        }
    }

    // ---- epilogue: C = acc + bias ----
    #pragma unroll
    for (int mt = 0; mt < 4; ++mt) {
        #pragma unroll
        for (int nt = 0; nt < 4; ++nt) {
            int r0  = rowBase + wm + mt * 16 + g;
            int col = wn + nt * 8 + tg * 2;
            float b0 = bias[colB + col], b1 = bias[colB + col + 1];
            float2 v0 = make_float2(acc[mt][nt][0] + b0, acc[mt][nt][1] + b1);
            float2 v1 = make_float2(acc[mt][nt][2] + b0, acc[mt][nt][3] + b1);
            *(float2*)(C + (size_t)r0 * ldc + colC + col) = v0;
            *(float2*)(C + (size_t)(r0 + 8) * ldc + colC + col) = v1;
        }
    }
}

__global__ __launch_bounds__(256) void qkv_gemm_tc(
    const float* __restrict__ x,
    const float* __restrict__ Wq, const float* __restrict__ bq,
    const float* __restrict__ Wk, const float* __restrict__ bk,
    const float* __restrict__ Wv, const float* __restrict__ bv)
{
    const int y  = blockIdx.y;         // 0..11
    const int z  = y >> 2;             // which weight
    const int nc = (y & 3) * BN;       // col block within D_WM
    const float* Bw = (z == 0) ? Wq : (z == 1) ? Wk : Wv;
    const float* bi = (z == 0) ? bq : (z == 1) ? bk : bv;
    tc_gemm_body(x, Bw, bi, g_qkv, DIM, QKV_LD,
                 blockIdx.x * BM, nc, z * DWM + nc, DIM / BK);
}

__global__ __launch_bounds__(256) void out_gemm_tc(
    const float* __restrict__ Wo, const float* __restrict__ bo,
    float* __restrict__ y)
{
    tc_gemm_body(g_att, Wo, bo, y, DWM, DIM,
                 blockIdx.x * BM, blockIdx.y * BN, blockIdx.y * BN, DWM / BK);
}

// ---------------- Attention kernel: one CTA per batch row --------------------
__global__ __launch_bounds__(256) void attn_kernel(
    const float* __restrict__ wmK, const float* __restrict__ wmV,
    const void* __restrict__ validIn,
    const void* __restrict__ resetIn,
    const int* __restrict__ ptrIn)
{
    __shared__ float  q_s[DWM];
    __shared__ float  att_s[NH][WIN];
    __shared__ float4 part_s[128];
    __shared__ unsigned char valid_s[WIN];

    const int b     = blockIdx.x;
    const int tid   = threadIdx.x;   // 256
    const int lane  = tid & 31;
    const int warp  = tid >> 5;      // 8 warps == 8 heads
    const int lane4 = lane & 15;
    const int half  = lane >> 4;     // 0/1

    const int mode = bool_mode((const unsigned char*)validIn);
    const bool rs = read_bool(resetIn, b, mode);
    const int  p  = rs ? 0 : ptrIn[b];

    const float* qrow  = g_qkv + (size_t)b * QKV_LD;
    const float* knew  = qrow + DWM;
    const float* vnew  = qrow + 2 * DWM;
    const float* Kbase = wmK + (size_t)b * WIN * DWM;
    const float* Vbase = wmV + (size_t)b * WIN * DWM;

    for (int i = tid; i < DWM; i += 256) q_s[i] = qrow[i];
    if (tid < WIN)
        valid_s[tid] = read_bool(validIn, (size_t)b * WIN + tid, mode) ? 1 : 0;
    __syncthreads();

    const float NEG_INF = __int_as_float(0xff800000);

    // ---- phase 1: logits. warp h: 16-lane split, 2 rows per pass, float4 ----
    {
        const int h = warp;
        float4 qv = *(const float4*)(q_s + h * HD + lane4 * 4);
        const float* kp = Kbase + h * HD + lane4 * 4;
        for (int w0 = 0; w0 < WIN; w0 += 8) {
            float s[4];
            #pragma unroll
            for (int u = 0; u < 4; ++u) {
                int w = w0 + 2 * u + half;
                float4 kv = __ldcs((const float4*)(kp + (size_t)w * DWM));
                s[u] = kv.x * qv.x + kv.y * qv.y + kv.z * qv.z + kv.w * qv.w;
            }
            #pragma unroll
            for (int u = 0; u < 4; ++u) {
                #pragma unroll
                for (int o = 1; o < 16; o <<= 1)
                    s[u] += __shfl_xor_sync(0xffffffffu, s[u], o);
            }
            if (lane4 == 0) {
                #pragma unroll
                for (int u = 0; u < 4; ++u) {
                    int w = w0 + 2 * u + half;
                    bool val = !rs && (valid_s[w] != 0);
                    att_s[h][w] = val ? s[u] * ATT_SCALE : NEG_INF;
                }
            }
        }
        // substitute fresh k at slot p (always valid)
        {
            float4 kv = *(const float4*)(knew + h * HD + lane4 * 4);
            float s = (half == 0)
                ? (kv.x * qv.x + kv.y * qv.y + kv.z * qv.z + kv.w * qv.w) : 0.f;
            #pragma unroll
            for (int o = 1; o < 16; o <<= 1)
                s += __shfl_xor_sync(0xffffffffu, s, o);
            if (lane == 0) att_s[h][p] = s * ATT_SCALE;
        }
    }
    __syncthreads();

    // ---- phase 2: per-head softmax (warp h) ----
    {
        const int h = warp;
        float e[8];
        float m = NEG_INF;
        #pragma unroll
        for (int j = 0; j < 8; ++j) {
            e[j] = att_s[h][lane + 32 * j];
            m = fmaxf(m, e[j]);
        }
        #pragma unroll
        for (int o = 16; o > 0; o >>= 1)
            m = fmaxf(m, __shfl_xor_sync(0xffffffffu, m, o));
        float sum = 0.f;
        #pragma unroll
        for (int j = 0; j < 8; ++j) {
            e[j] = __expf(e[j] - m);
            sum += e[j];
        }
        #pragma unroll
        for (int o = 16; o > 0; o >>= 1)
            sum += __shfl_xor_sync(0xffffffffu, sum, o);
        float inv = (sum > 0.f) ? (1.0f / sum) : 0.f;
        #pragma unroll
        for (int j = 0; j < 8; ++j)
            att_s[h][lane + 32 * j] = e[j] * inv;
    }
    __syncthreads();

    // ---- phase 3: AV. two 128-thread groups split the window, float4 ----
    {
        const int t  = tid & 127;
        const int gr = tid >> 7;       // 0: w 0..127, 1: w 128..255
        const int d  = t * 4;
        const int h  = t >> 4;
        float4 acc = make_float4(0.f, 0.f, 0.f, 0.f);
        const float* vp = Vbase + (size_t)(gr * 128) * DWM + d;
        const float* pw_base = &att_s[h][gr * 128];
        for (int w0 = 0; w0 < 128; w0 += 8) {
            float4 vv[8];
            #pragma unroll
            for (int u = 0; u < 8; ++u)
                vv[u] = __ldcs((const float4*)(vp + (size_t)(w0 + u) * DWM));
            #pragma unroll
            for (int u = 0; u < 8; ++u) {
                float pw = pw_base[w0 + u];
                acc.x = fmaf(pw, vv[u].x, acc.x);
                acc.y = fmaf(pw, vv[u].y, acc.y);
                acc.z = fmaf(pw, vv[u].z, acc.z);
                acc.w = fmaf(pw, vv[u].w, acc.w);
            }
        }
        // correction at slot p (owned by its group): replace stored V by fresh v
        if ((p >> 7) == gr) {
            float4 vold = *(const float4*)(Vbase + (size_t)p * DWM + d);
            float4 vn   = *(const float4*)(vnew + d);
            float pw = att_s[h][p];
            acc.x = fmaf(pw, vn.x - vold.x, acc.x);
            acc.y = fmaf(pw, vn.y - vold.y, acc.y);
            acc.z = fmaf(pw, vn.z - vold.z, acc.z);
            acc.w = fmaf(pw, vn.w - vold.w, acc.w);
        }
        if (gr == 1) part_s[t] = acc;
        __syncthreads();
        if (gr == 0) {
            float4 o = part_s[t];
            acc.x += o.x; acc.y += o.y; acc.z += o.z; acc.w += o.w;
            *(float4*)(g_att + (size_t)b * DWM + d) = acc;
        }
    }
}

// ---------------- launcher ---------------------------------------------------
extern "C" void kernel_launch(void* const* d_in, const int* in_sizes, int n_in,
                              void* d_out, int out_size)
{
    const float* x     = (const float*)d_in[0];
    const void*  reset = d_in[1];
    const float* wmK   = (const float*)d_in[2];
    const float* wmV   = (const float*)d_in[3];
    const void*  valid = d_in[4];
    const int*   ptr   = (const int*)d_in[5];
    const float* Wq    = (const float*)d_in[6];
    const float* bq    = (const float*)d_in[7];
    const float* Wk    = (const float*)d_in[8];
    const float* bk    = (const float*)d_in[9];
    const float* Wv    = (const float*)d_in[10];
    const float* bv    = (const float*)d_in[11];
    const float* Wo    = (const float*)d_in[12];
    const float* bo    = (const float*)d_in[13];
    float*       y     = (float*)d_out;

    // opt-in to 64 KB dynamic smem (attribute set, not device work; idempotent)
    cudaFuncSetAttribute(qkv_gemm_tc, cudaFuncAttributeMaxDynamicSharedMemorySize, TCSM_BYTES);
    cudaFuncSetAttribute(out_gemm_tc, cudaFuncAttributeMaxDynamicSharedMemorySize, TCSM_BYTES);

    dim3 gQKV(BSZ / BM, 12);            // 16 x 12 = 192 CTAs
    qkv_gemm_tc<<<gQKV, 256, TCSM_BYTES>>>(x, Wq, bq, Wk, bk, Wv, bv);

    attn_kernel<<<BSZ, 256>>>(wmK, wmV, valid, reset, ptr);

    dim3 gOut(BSZ / BM, DIM / BN);      // 16 x 8 = 128 CTAs
    out_gemm_tc<<<gOut, 256, TCSM_BYTES>>>(Wo, bo, y);
}

// round 7
// speedup vs baseline: 1.4735x; 1.0297x over previous
#include <cuda_runtime.h>
#include <cstdint>

// Problem constants
#define BSZ   2048
#define DIM   1024
#define DWM   512
#define WIN   256
#define NH    8
#define HD    64
#define QKV_LD 1536
#define ATT_SCALE 0.125f

// Scratch (device globals: allocation-free rule)
__device__ float g_qkv[(size_t)BSZ * QKV_LD];   // 12 MB
__device__ float g_att[(size_t)BSZ * DWM];      // 4 MB

// ---------------- bool dtype helpers ------------------------------------------
// bool arrays may be stored as uint8 / int32 / float32; wm_valid is all-True so
// its first bytes identify the dtype. Computed per-CTA (cheap, deterministic).
__device__ __forceinline__ int bool_mode(const unsigned char* valid)
{
    unsigned char b0 = valid[0], b1 = valid[1];
    return (b0 == 0) ? 2 : (b1 != 0 ? 0 : 1);   // 0=u8, 1=i32, 2=f32
}
__device__ __forceinline__ bool read_bool(const void* p, long idx, int mode)
{
    if (mode == 1) return ((const int*)p)[idx] != 0;
    if (mode == 2) return ((const float*)p)[idx] != 0.0f;
    return ((const unsigned char*)p)[idx] != 0;
}

// ---------------- tf32 helpers ------------------------------------------------
__device__ __forceinline__ uint32_t f2tf32(float f) {
    uint32_t u;
    asm("cvt.rna.tf32.f32 %0, %1;" : "=r"(u) : "f"(f));
    return u;
}
__device__ __forceinline__ void mma_tf32(float* d, const uint32_t* a, const uint32_t* b) {
    asm volatile(
        "mma.sync.aligned.m16n8k8.row.col.f32.tf32.tf32.f32 "
        "{%0,%1,%2,%3},{%4,%5,%6,%7},{%8,%9},{%0,%1,%2,%3};\n"
        : "+f"(d[0]), "+f"(d[1]), "+f"(d[2]), "+f"(d[3])
        : "r"(a[0]), "r"(a[1]), "r"(a[2]), "r"(a[3]), "r"(b[0]), "r"(b[1]));
}

// ===================== tf32 mma.sync GEMM (NT + bias) =========================
// C[m,n] = sum_k A[m,k]*B[n,k] + bias[n]
// CTA tile 128x128, K-tile 32, 256 threads = 8 warps (2m x 4n), warp tile 64x32.
#define BM 128
#define BN 128
#define BK 32
#define A_FLOATS (BM * BK)               // 4096
#define B_FLOATS (BN * BK)               // 4096
#define BUF_FLOATS (A_FLOATS + B_FLOATS) // 8192
#define TCSM_BYTES (2 * BUF_FLOATS * 4)  // 65536 (opt-in)

__device__ __forceinline__ void tc_gemm_body(
    const float* __restrict__ A, const float* __restrict__ Bw,
    const float* __restrict__ bias, float* __restrict__ C,
    int K, int ldc, int rowBase, int colB, int colC, int niter)
{
    extern __shared__ float smem[];
    const int tid  = threadIdx.x;
    const int lane = tid & 31;
    const int warp = tid >> 5;
    const int g    = lane >> 2;          // 0..7
    const int tg   = lane & 3;           // 0..3
    const int wm   = (warp >> 2) * 64;   // 0,64
    const int wn   = (warp & 3) * 32;    // 0,32,64,96

    const float* Abase = A  + (size_t)rowBase * K;
    const float* Bbase = Bw + (size_t)colB  * K;

    float acc[4][4][4];
    #pragma unroll
    for (int mt = 0; mt < 4; ++mt)
        #pragma unroll
        for (int nt = 0; nt < 4; ++nt)
            #pragma unroll
            for (int r = 0; r < 4; ++r) acc[mt][nt][r] = 0.f;

    float4 pa[4], pb[4];

    // ---- prefetch + store tile 0 ----
    #pragma unroll
    for (int i = 0; i < 4; ++i) {
        int idx = tid + (i << 8), row = idx >> 3, q = idx & 7;
        pa[i] = *(const float4*)(Abase + (size_t)row * K + (q << 2));
        pb[i] = *(const float4*)(Bbase + (size_t)row * K + (q << 2));
    }
    {
        float* Abuf = smem;
        float* Bbuf = smem + A_FLOATS;
        #pragma unroll
        for (int i = 0; i < 4; ++i) {
            int idx = tid + (i << 8), row = idx >> 3, q = idx & 7;
            uint4 ta, tb;
            ta.x = f2tf32(pa[i].x); ta.y = f2tf32(pa[i].y);
            ta.z = f2tf32(pa[i].z); ta.w = f2tf32(pa[i].w);
            tb.x = f2tf32(pb[i].x); tb.y = f2tf32(pb[i].y);
            tb.z = f2tf32(pb[i].z); tb.w = f2tf32(pb[i].w);
            int soff = row * BK + ((q ^ (row & 7)) << 2);
            *(uint4*)(Abuf + soff) = ta;
            *(uint4*)(Bbuf + soff) = tb;
        }
    }
    __syncthreads();

    for (int it = 0; it < niter; ++it) {
        const int buf = it & 1;
        if (it + 1 < niter) {
            const float* An = Abase + (it + 1) * BK;
            const float* Bn = Bbase + (it + 1) * BK;
            #pragma unroll
            for (int i = 0; i < 4; ++i) {
                int idx = tid + (i << 8), row = idx >> 3, q = idx & 7;
                pa[i] = *(const float4*)(An + (size_t)row * K + (q << 2));
                pb[i] = *(const float4*)(Bn + (size_t)row * K + (q << 2));
            }
        }
        {
            const uint32_t* Abuf = (const uint32_t*)(smem + buf * BUF_FLOATS);
            const uint32_t* Bbuf = Abuf + A_FLOATS;
            #pragma unroll
            for (int ks = 0; ks < 4; ++ks) {
                uint32_t af[4][4], bf[4][2];
                const int g0 = ((2 * ks) ^ g) << 2;
                const int g1 = ((2 * ks + 1) ^ g) << 2;
                #pragma unroll
                for (int mt = 0; mt < 4; ++mt) {
                    int r0 = wm + mt * 16 + g;
                    int r1 = r0 + 8;
                    af[mt][0] = Abuf[r0 * BK + g0 + tg];
                    af[mt][1] = Abuf[r1 * BK + g0 + tg];
                    af[mt][2] = Abuf[r0 * BK + g1 + tg];
                    af[mt][3] = Abuf[r1 * BK + g1 + tg];
                }
                #pragma unroll
                for (int nt = 0; nt < 4; ++nt) {
                    int n = wn + nt * 8 + g;
                    bf[nt][0] = Bbuf[n * BK + g0 + tg];
                    bf[nt][1] = Bbuf[n * BK + g1 + tg];
                }
                #pragma unroll
                for (int mt = 0; mt < 4; ++mt)
                    #pragma unroll
                    for (int nt = 0; nt < 4; ++nt)
                        mma_tf32(acc[mt][nt], af[mt], bf[nt]);
            }
        }
        if (it + 1 < niter) {
            float* Abuf = smem + (buf ^ 1) * BUF_FLOATS;
            float* Bbuf = Abuf + A_FLOATS;
            #pragma unroll
            for (int i = 0; i < 4; ++i) {
                int idx = tid + (i << 8), row = idx >> 3, q = idx & 7;
                uint4 ta, tb;
                ta.x = f2tf32(pa[i].x); ta.y = f2tf32(pa[i].y);
                ta.z = f2tf32(pa[i].z); ta.w = f2tf32(pa[i].w);
                tb.x = f2tf32(pb[i].x); tb.y = f2tf32(pb[i].y);
                tb.z = f2tf32(pb[i].z); tb.w = f2tf32(pb[i].w);
                int soff = row * BK + ((q ^ (row & 7)) << 2);
                *(uint4*)(Abuf + soff) = ta;
                *(uint4*)(Bbuf + soff) = tb;
            }
            __syncthreads();
        }
    }

    // ---- epilogue: C = acc + bias ----
    #pragma unroll
    for (int mt = 0; mt < 4; ++mt) {
        #pragma unroll
        for (int nt = 0; nt < 4; ++nt) {
            int r0  = rowBase + wm + mt * 16 + g;
            int col = wn + nt * 8 + tg * 2;
            float b0 = bias[colB + col], b1 = bias[colB + col + 1];
            float2 v0 = make_float2(acc[mt][nt][0] + b0, acc[mt][nt][1] + b1);
            float2 v1 = make_float2(acc[mt][nt][2] + b0, acc[mt][nt][3] + b1);
            *(float2*)(C + (size_t)r0 * ldc + colC + col) = v0;
            *(float2*)(C + (size_t)(r0 + 8) * ldc + colC + col) = v1;
        }
    }
}

__global__ __launch_bounds__(256) void qkv_gemm_tc(
    const float* __restrict__ x,
    const float* __restrict__ Wq, const float* __restrict__ bq,
    const float* __restrict__ Wk, const float* __restrict__ bk,
    const float* __restrict__ Wv, const float* __restrict__ bv)
{
    const int y  = blockIdx.y;         // 0..11
    const int z  = y >> 2;             // which weight
    const int nc = (y & 3) * BN;       // col block within D_WM
    const float* Bw = (z == 0) ? Wq : (z == 1) ? Wk : Wv;
    const float* bi = (z == 0) ? bq : (z == 1) ? bk : bv;
    tc_gemm_body(x, Bw, bi, g_qkv, DIM, QKV_LD,
                 blockIdx.x * BM, nc, z * DWM + nc, DIM / BK);
}

__global__ __launch_bounds__(256) void out_gemm_tc(
    const float* __restrict__ Wo, const float* __restrict__ bo,
    float* __restrict__ y)
{
    tc_gemm_body(g_att, Wo, bo, y, DWM, DIM,
                 blockIdx.x * BM, blockIdx.y * BN, blockIdx.y * BN, DWM / BK);
}

// ---------------- Attention kernel (R4-proven form): one CTA per batch row ---
__global__ __launch_bounds__(256) void attn_kernel(
    const float* __restrict__ wmK, const float* __restrict__ wmV,
    const void* __restrict__ validIn,
    const void* __restrict__ resetIn,
    const int* __restrict__ ptrIn)
{
    __shared__ float q_s[DWM];
    __shared__ float att_s[NH][WIN];
    __shared__ unsigned char valid_s[WIN];

    const int b    = blockIdx.x;
    const int tid  = threadIdx.x;   // 256
    const int lane = tid & 31;
    const int warp = tid >> 5;      // 8 warps == 8 heads

    const int mode = bool_mode((const unsigned char*)validIn);
    const bool rs = read_bool(resetIn, b, mode);
    const int  p  = rs ? 0 : ptrIn[b];

    const float* qrow  = g_qkv + (size_t)b * QKV_LD;
    const float* knew  = qrow + DWM;
    const float* vnew  = qrow + 2 * DWM;
    const float* Kbase = wmK + (size_t)b * WIN * DWM;
    const float* Vbase = wmV + (size_t)b * WIN * DWM;

    for (int i = tid; i < DWM; i += 256) q_s[i] = qrow[i];
    if (tid < WIN)
        valid_s[tid] = read_bool(validIn, (size_t)b * WIN + tid, mode) ? 1 : 0;
    __syncthreads();

    const float NEG_INF = __int_as_float(0xff800000);

    // ---- phase 1: logits (uniform over stored K; slot p patched after) ----
    {
        const int h = warp;
        float2 qv = *(const float2*)(q_s + h * HD + lane * 2);
        const float2* kp = (const float2*)(Kbase + h * HD + lane * 2);
        for (int w0 = 0; w0 < WIN; w0 += 8) {
            float s[8];
            #pragma unroll
            for (int u = 0; u < 8; ++u) {
                float2 kv = __ldcs(kp + (size_t)(w0 + u) * (DWM / 2));
                s[u] = kv.x * qv.x + kv.y * qv.y;
            }
            #pragma unroll
            for (int u = 0; u < 8; ++u) {
                #pragma unroll
                for (int o = 16; o > 0; o >>= 1)
                    s[u] += __shfl_xor_sync(0xffffffffu, s[u], o);
            }
            if (lane == 0) {
                #pragma unroll
                for (int u = 0; u < 8; ++u) {
                    int w = w0 + u;
                    bool val = !rs && (valid_s[w] != 0);
                    att_s[h][w] = val ? s[u] * ATT_SCALE : NEG_INF;
                }
            }
        }
        // substitute fresh k at slot p (always valid)
        {
            float2 kv = *(const float2*)(knew + h * HD + lane * 2);
            float s = kv.x * qv.x + kv.y * qv.y;
            #pragma unroll
            for (int o = 16; o > 0; o >>= 1)
                s += __shfl_xor_sync(0xffffffffu, s, o);
            if (lane == 0) att_s[h][p] = s * ATT_SCALE;
        }
    }
    __syncthreads();

    // ---- phase 2: per-head softmax (warp h) ----
    {
        const int h = warp;
        float e[8];
        float m = NEG_INF;
        #pragma unroll
        for (int j = 0; j < 8; ++j) {
            e[j] = att_s[h][lane + 32 * j];
            m = fmaxf(m, e[j]);
        }
        #pragma unroll
        for (int o = 16; o > 0; o >>= 1)
            m = fmaxf(m, __shfl_xor_sync(0xffffffffu, m, o));
        float sum = 0.f;
        #pragma unroll
        for (int j = 0; j < 8; ++j) {
            e[j] = __expf(e[j] - m);
            sum += e[j];
        }
        #pragma unroll
        for (int o = 16; o > 0; o >>= 1)
            sum += __shfl_xor_sync(0xffffffffu, sum, o);
        float inv = (sum > 0.f) ? (1.0f / sum) : 0.f;
        #pragma unroll
        for (int j = 0; j < 8; ++j)
            att_s[h][lane + 32 * j] = e[j] * inv;
    }
    __syncthreads();

    // ---- phase 3: AV, uniform over stored V; correction for slot p ----
    {
        const int d = tid * 2;
        const int h = tid >> 5;
        float ax = 0.f, ay = 0.f;
        const float2* vp = (const float2*)(Vbase + d);
        for (int w0 = 0; w0 < WIN; w0 += 8) {
            float2 vv[8];
            #pragma unroll
            for (int u = 0; u < 8; ++u)
                vv[u] = __ldcs(vp + (size_t)(w0 + u) * (DWM / 2));
            #pragma unroll
            for (int u = 0; u < 8; ++u) {
                float pw = att_s[h][w0 + u];
                ax = fmaf(pw, vv[u].x, ax);
                ay = fmaf(pw, vv[u].y, ay);
            }
        }
        {
            float2 vold = *(const float2*)(Vbase + (size_t)p * DWM + d);
            float2 vn   = *(const float2*)(vnew + d);
            float pw = att_s[h][p];
            ax = fmaf(pw, vn.x - vold.x, ax);
            ay = fmaf(pw, vn.y - vold.y, ay);
        }
        *(float2*)(g_att + (size_t)b * DWM + d) = make_float2(ax, ay);
    }
}

// ---------------- launcher ---------------------------------------------------
extern "C" void kernel_launch(void* const* d_in, const int* in_sizes, int n_in,
                              void* d_out, int out_size)
{
    const float* x     = (const float*)d_in[0];
    const void*  reset = d_in[1];
    const float* wmK   = (const float*)d_in[2];
    const float* wmV   = (const float*)d_in[3];
    const void*  valid = d_in[4];
    const int*   ptr   = (const int*)d_in[5];
    const float* Wq    = (const float*)d_in[6];
    const float* bq    = (const float*)d_in[7];
    const float* Wk    = (const float*)d_in[8];
    const float* bk    = (const float*)d_in[9];
    const float* Wv    = (const float*)d_in[10];
    const float* bv    = (const float*)d_in[11];
    const float* Wo    = (const float*)d_in[12];
    const float* bo    = (const float*)d_in[13];
    float*       y     = (float*)d_out;

    // opt-in to 64 KB dynamic smem (host attribute set; idempotent)
    cudaFuncSetAttribute(qkv_gemm_tc, cudaFuncAttributeMaxDynamicSharedMemorySize, TCSM_BYTES);
    cudaFuncSetAttribute(out_gemm_tc, cudaFuncAttributeMaxDynamicSharedMemorySize, TCSM_BYTES);

    dim3 gQKV(BSZ / BM, 12);            // 16 x 12 = 192 CTAs
    qkv_gemm_tc<<<gQKV, 256, TCSM_BYTES>>>(x, Wq, bq, Wk, bk, Wv, bv);

    attn_kernel<<<BSZ, 256>>>(wmK, wmV, valid, reset, ptr);

    dim3 gOut(BSZ / BM, DIM / BN);      // 16 x 8 = 128 CTAs
    out_gemm_tc<<<gOut, 256, TCSM_BYTES>>>(Wo, bo, y);
}